// round 15
// baseline (speedup 1.0000x reference)
#include <cuda_runtime.h>
#include <cuda_bf16.h>
#include <math.h>
#include <stdint.h>

#define Bv   4
#define Cv   64
#define Hv   160
#define Wv   160
#define HWv  25600
#define KKv  9
#define OMC  27
#define CKK  576

#define MT    128
#define TPB   256
#define CKC   64
#define NCH   9

// fused smem map (bytes)
#define FS_SC    0
#define FS_SH    256
#define FS_BIAS  512
#define FS_WGT   1024       // float4[1152] = 18432
#define FS_BASE  19456      // int[1152]
#define FS_AH    24576      // 16384
#define FS_AL    40960      // 16384
#define FS_BH    57344      // 8192
#define FS_BL    65536      // 8192
#define FS_OM    24576      // overlaps AH (dead between phases)
#define OMST     29
#define FS_TOT   73728

__device__ float          g_mid[Bv*Cv*HWv];
__device__ __nv_bfloat16  g_midh[Bv*Cv*HWv];
__device__ __align__(16) __nv_bfloat16 g_wh1[Cv*CKK], g_wl1[Cv*CKK];
__device__ __align__(16) __nv_bfloat16 g_wh2[Cv*CKK], g_wl2[Cv*CKK];
__device__ __align__(16) __nv_bfloat16 g_omh1[32*CKK];
__device__ __align__(16) __nv_bfloat16 g_omh2[32*CKK];

__device__ __forceinline__ float gelu_exact(float v) {
    return 0.5f * v * (1.0f + erff(v * 0.70710678118654752f));
}
__device__ __forceinline__ uint32_t split_pack(float v) {
    __nv_bfloat16 h = __float2bfloat16(v);
    __nv_bfloat16 l = __float2bfloat16(v - __bfloat162float(h));
    return (uint32_t)__bfloat16_as_ushort(h) | ((uint32_t)__bfloat16_as_ushort(l) << 16);
}
__device__ __forceinline__ uint32_t pack_bf16x2(float lo, float hi) {
    uint32_t r;
    asm("cvt.rn.bf16x2.f32 %0, %1, %2;" : "=r"(r) : "f"(hi), "f"(lo));
    return r;
}
__device__ __forceinline__ uint32_t smem_u32(const void* p) {
    uint32_t a;
    asm("{ .reg .u64 t; cvta.to.shared.u64 t, %1; cvt.u32.u64 %0, t; }" : "=r"(a) : "l"(p));
    return a;
}
__device__ __forceinline__ void mma_bf16(float* d,
    uint32_t a0, uint32_t a1, uint32_t a2, uint32_t a3, uint32_t b0, uint32_t b1)
{
    asm volatile(
        "mma.sync.aligned.m16n8k16.row.col.f32.bf16.bf16.f32 "
        "{%0,%1,%2,%3},{%4,%5,%6,%7},{%8,%9},{%0,%1,%2,%3};"
        : "+f"(d[0]), "+f"(d[1]), "+f"(d[2]), "+f"(d[3])
        : "r"(a0), "r"(a1), "r"(a2), "r"(a3), "r"(b0), "r"(b1));
}
__device__ __forceinline__ void ldm_x4(uint32_t& r0, uint32_t& r1, uint32_t& r2, uint32_t& r3, uint32_t addr) {
    asm volatile("ldmatrix.sync.aligned.m8n8.x4.shared.b16 {%0,%1,%2,%3}, [%4];"
                 : "=r"(r0), "=r"(r1), "=r"(r2), "=r"(r3) : "r"(addr));
}
__device__ __forceinline__ uint32_t swz(int row, int cq) {
    return (uint32_t)(row*128 + ((cq ^ (row & 7)) << 4));
}

// ---------------------------------------------------------------------------
__global__ void prep_kernel(const float* __restrict__ wd1, const float* __restrict__ wd2,
                            const float* __restrict__ wom1, const float* __restrict__ wom2)
{
    int i = blockIdx.x * 256 + threadIdx.x;
    if (i < Cv*CKK) {
        int o = i / CKK, r = i - o*CKK;
        int c = r / 9, k = r - 9*c;
        int dst = o*CKK + k*64 + c;
        float v1 = wd1[i];
        __nv_bfloat16 h1 = __float2bfloat16(v1);
        g_wh1[dst] = h1;
        g_wl1[dst] = __float2bfloat16(v1 - __bfloat162float(h1));
        float v2 = wd2[i];
        __nv_bfloat16 h2 = __float2bfloat16(v2);
        g_wh2[dst] = h2;
        g_wl2[dst] = __float2bfloat16(v2 - __bfloat162float(h2));
    }
    if (i < 32*CKK) {
        int o = i / CKK, r = i - o*CKK;
        int c = r / 9, k = r - 9*c;
        int dst = o*CKK + k*64 + c;
        g_omh1[dst] = __float2bfloat16((i < OMC*CKK) ? wom1[i] : 0.f);
        g_omh2[dst] = __float2bfloat16((i < OMC*CKK) ? wom2[i] : 0.f);
    }
}

// ---------------------------------------------------------------------------
// Fused BasicBlock half with cross-chunk register prefetch.
// ---------------------------------------------------------------------------
template<bool F32IN>
__global__ __launch_bounds__(TPB, 3) void fused_kernel(
    const void* __restrict__ omin,
    const __nv_bfloat16* __restrict__ omwh,
    const float* __restrict__ ombias,
    const float* __restrict__ src,
    const __nv_bfloat16* __restrict__ wh,
    const __nv_bfloat16* __restrict__ wl,
    const float* __restrict__ bng,
    const float* __restrict__ bnb,
    const float* __restrict__ bnm,
    const float* __restrict__ bnv,
    const float* __restrict__ identity,
    float* __restrict__ out,
    __nv_bfloat16* __restrict__ midh)
{
    extern __shared__ char smem[];
    const uint32_t sbu = smem_u32(smem);
    float*  sSc   = (float*)(smem + FS_SC);
    float*  sSh   = (float*)(smem + FS_SH);
    float*  sbias = (float*)(smem + FS_BIAS);
    float4* sWgt  = (float4*)(smem + FS_WGT);
    int*    sBase = (int*)(smem + FS_BASE);
    float*  sOm   = (float*)(smem + FS_OM);

    const int tid  = threadIdx.x, wid = tid >> 5, lane = tid & 31;
    const int g    = lane >> 2, tq = lane & 3;
    const int b    = blockIdx.y;
    const int P0   = blockIdx.x * MT;

    if (tid < 64) {
        float sc = bng[tid] * rsqrtf(bnv[tid] + 1e-5f);
        sSc[tid] = sc;
        sSh[tid] = bnb[tid] - bnm[tid]*sc;
    } else if (tid < 96) {
        int o = tid - 64;
        sbias[o] = (o < OMC) ? ombias[o] : 0.f;
    }

    const int pl = tid & 127, jh = tid >> 7;
    const int pg = P0 + pl;
    const int py = pg / Wv, px = pg - py*Wv;

    // ldmatrix lane geometry
    const int laneA = lane & 15;
    const int rowA = wid*16 + laneA;
    const int kbA  = (lane & 16) ? 1 : 0;
    const int rowB0 = (lane & 7) + ((lane & 16) ? 8 : 0);
    const int kbB   = (lane & 8) ? 1 : 0;

    // ===== Phase 1: offset/mask conv (1-pass bf16), prefetched =====
    {
        const size_t chbase = (size_t)b*Cv*HWv + (size_t)(jh*32)*HWv;
        const int oB = tid >> 3, cqB = tid & 7;   // B staging coords
        float acc[4][4];
        #pragma unroll
        for (int nt = 0; nt < 4; nt++)
            #pragma unroll
            for (int e = 0; e < 4; e++) acc[nt][e] = 0.f;

        float    pf[32];      // raw prefetched A loads (F32IN)
        uint32_t pfu[32];     // raw prefetched A loads (bf16)
        uint4    pB;          // prefetched B quad

        // preamble: issue chunk-0 loads
        {
            pB = *(const uint4*)(omwh + oB*CKK + 0*CKC + cqB*8);
            int yy = py + 0/3 - 1, xx = px + (0 % 3) - 1;
            bool val = ((unsigned)yy < (unsigned)Hv) && ((unsigned)xx < (unsigned)Wv);
            if (F32IN) {
                const float* p = (const float*)omin + chbase + yy*Wv + xx;
                #pragma unroll
                for (int j = 0; j < 32; j++) pf[j] = val ? __ldg(p + (size_t)j*HWv) : 0.f;
            } else {
                const __nv_bfloat16* p = (const __nv_bfloat16*)omin + chbase + yy*Wv + xx;
                #pragma unroll
                for (int j = 0; j < 32; j++)
                    pfu[j] = val ? (uint32_t)__bfloat16_as_ushort(__ldg(p + (size_t)j*HWv)) : 0u;
            }
        }

        for (int cc = 0; cc < NCH; cc++) {
            if (cc) __syncthreads();
            // commit B
            *(uint4*)(smem + FS_BH + swz(oB, cqB)) = pB;
            // commit A: pack prefetched loads
            #pragma unroll
            for (int q = 0; q < 4; q++) {
                uint32_t hq[4];
                #pragma unroll
                for (int wi = 0; wi < 4; wi++) {
                    int c0 = 8*q + 2*wi;
                    if (F32IN) hq[wi] = pack_bf16x2(pf[c0], pf[c0+1]);
                    else       hq[wi] = pfu[c0] | (pfu[c0+1] << 16);
                }
                *(uint4*)(smem + FS_AH + swz(pl, jh*4 + q)) = make_uint4(hq[0],hq[1],hq[2],hq[3]);
            }
            // issue next-chunk loads (overlap the MMA below)
            if (cc + 1 < NCH) {
                int cn = cc + 1;
                pB = *(const uint4*)(omwh + oB*CKK + cn*CKC + cqB*8);
                int yy = py + cn/3 - 1, xx = px + (cn % 3) - 1;
                bool val = ((unsigned)yy < (unsigned)Hv) && ((unsigned)xx < (unsigned)Wv);
                if (F32IN) {
                    const float* p = (const float*)omin + chbase + yy*Wv + xx;
                    #pragma unroll
                    for (int j = 0; j < 32; j++) pf[j] = val ? __ldg(p + (size_t)j*HWv) : 0.f;
                } else {
                    const __nv_bfloat16* p = (const __nv_bfloat16*)omin + chbase + yy*Wv + xx;
                    #pragma unroll
                    for (int j = 0; j < 32; j++)
                        pfu[j] = val ? (uint32_t)__bfloat16_as_ushort(__ldg(p + (size_t)j*HWv)) : 0u;
                }
            }
            __syncthreads();
            // mma: 1 pass, N=32
            #pragma unroll
            for (int ks = 0; ks < 4; ks++) {
                uint32_t aAH = sbu + FS_AH + swz(rowA, ks*2 + kbA);
                uint32_t aH0,aH1,aH2,aH3;
                ldm_x4(aH0,aH1,aH2,aH3, aAH);
                uint32_t aB0 = sbu + FS_BH + swz(rowB0, ks*2 + kbB);
                uint32_t aB1 = sbu + FS_BH + swz(16 + rowB0, ks*2 + kbB);
                uint32_t bh0,bh1,bh2,bh3;
                ldm_x4(bh0,bh1,bh2,bh3, aB0);
                mma_bf16(acc[0], aH0,aH1,aH2,aH3, bh0,bh1);
                mma_bf16(acc[1], aH0,aH1,aH2,aH3, bh2,bh3);
                ldm_x4(bh0,bh1,bh2,bh3, aB1);
                mma_bf16(acc[2], aH0,aH1,aH2,aH3, bh0,bh1);
                mma_bf16(acc[3], aH0,aH1,aH2,aH3, bh2,bh3);
            }
        }

        __syncthreads();
        #pragma unroll
        for (int nt = 0; nt < 4; nt++) {
            #pragma unroll
            for (int e = 0; e < 4; e++) {
                int o = nt*8 + 2*tq + (e & 1);
                if (o < OMC) {
                    int p = wid*16 + g + (e >> 1)*8;
                    sOm[p*OMST + o] = acc[nt][e] + sbias[o];
                }
            }
        }
    }
    __syncthreads();

    // ===== Phase 2: gather tables from smem om =====
    for (int idx = tid; idx < KKv*MT; idx += TPB) {
        int k = idx >> 7, plt = idx & 127;
        int pxg2 = P0 + plt;
        int y = pxg2 / Wv, x = pxg2 - y*Wv;
        float dy = sOm[plt*OMST + 2*k];
        float dx = sOm[plt*OMST + 2*k+1];
        float mr = sOm[plt*OMST + 18+k];
        float m  = 1.f / (1.f + expf(-mr));
        float pyf = (float)y - 1.f + (float)(k/3) + dy;
        float pxf = (float)x - 1.f + (float)(k%3) + dx;
        float yf = floorf(pyf), xf = floorf(pxf);
        float ly = pyf - yf, lx = pxf - xf;
        int iy0 = (int)yf, ix0 = (int)xf;
        float vy0 = ((unsigned)iy0     < (unsigned)Hv) ? 1.f : 0.f;
        float vy1 = ((unsigned)(iy0+1) < (unsigned)Hv) ? 1.f : 0.f;
        float vx0 = ((unsigned)ix0     < (unsigned)Wv) ? 1.f : 0.f;
        float vx1 = ((unsigned)(ix0+1) < (unsigned)Wv) ? 1.f : 0.f;
        sWgt[idx] = make_float4((1.f-ly)*(1.f-lx)*m*vy0*vx0,
                                (1.f-ly)*lx      *m*vy0*vx1,
                                ly      *(1.f-lx)*m*vy1*vx0,
                                ly      *lx      *m*vy1*vx1);
        int iy0c = min(max(iy0,0),Hv-1), ix0c = min(max(ix0,0),Wv-1);
        int dy1 = (iy0 >= 0 && iy0 <= Hv-2) ? 1 : 0;
        int dx1 = (ix0 >= 0 && ix0 <= Wv-2) ? 1 : 0;
        sBase[idx] = iy0c | (ix0c<<8) | (dy1<<16) | (dx1<<17);
    }
    __syncthreads();

    // ===== Phase 3: DCN (3-pass, 32px x 32o warp tiles), B prefetched =====
    const float* srcB = src + (size_t)b*Cv*HWv + (size_t)jh*32*HWv;
    const int wq = wid & 3, wn = wid >> 2;
    const int oB2 = tid >> 3, cqB2 = tid & 7;     // B staging coords (o 0..31 via 2 its)

    float acc[2][4][4];
    #pragma unroll
    for (int mt = 0; mt < 2; mt++)
        #pragma unroll
        for (int nt = 0; nt < 4; nt++)
            #pragma unroll
            for (int e = 0; e < 4; e++) acc[mt][nt][e] = 0.f;

    uint4 pBH[2], pBL[2];
    #pragma unroll
    for (int it = 0; it < 2; it++) {
        int o = it*32 + oB2;
        int gofs = o*CKK + 0*CKC + cqB2*8;
        pBH[it] = *(const uint4*)(wh + gofs);
        pBL[it] = *(const uint4*)(wl + gofs);
    }

    for (int cc = 0; cc < NCH; cc++) {
        if (cc) __syncthreads();

        // commit B
        #pragma unroll
        for (int it = 0; it < 2; it++) {
            uint32_t d = swz(it*32 + oB2, cqB2);
            *(uint4*)(smem + FS_BH + d) = pBH[it];
            *(uint4*)(smem + FS_BL + d) = pBL[it];
        }
        // issue next-chunk B loads (overlap sampling + MMA)
        if (cc + 1 < NCH) {
            #pragma unroll
            for (int it = 0; it < 2; it++) {
                int o = it*32 + oB2;
                int gofs = o*CKK + (cc+1)*CKC + cqB2*8;
                pBH[it] = *(const uint4*)(wh + gofs);
                pBL[it] = *(const uint4*)(wl + gofs);
            }
        }

        // sample A chunk: fixed tap cc
        {
            int gi = cc*MT + pl;
            float4 cw = sWgt[gi];
            int ev = sBase[gi];
            int iy0 = ev & 255, ix0 = (ev>>8) & 255;
            int iy1 = iy0 + ((ev>>16)&1), ix1 = ix0 + ((ev>>17)&1);
            const float* pA = srcB + iy0*Wv + ix0;
            const float* pB = srcB + iy0*Wv + ix1;
            const float* pC = srcB + iy1*Wv + ix0;
            const float* pD = srcB + iy1*Wv + ix1;
            #pragma unroll
            for (int q = 0; q < 4; q++) {
                float vA[8], vB[8], vC[8], vD[8];
                #pragma unroll
                for (int ci = 0; ci < 8; ci++) {
                    size_t co = (size_t)(8*q + ci)*HWv;
                    vA[ci] = __ldg(pA + co);
                    vB[ci] = __ldg(pB + co);
                    vC[ci] = __ldg(pC + co);
                    vD[ci] = __ldg(pD + co);
                }
                uint32_t hq[4], lq[4];
                #pragma unroll
                for (int wi = 0; wi < 4; wi++) {
                    float s0 = cw.x*vA[2*wi]   + cw.y*vB[2*wi]
                             + cw.z*vC[2*wi]   + cw.w*vD[2*wi];
                    float s1 = cw.x*vA[2*wi+1] + cw.y*vB[2*wi+1]
                             + cw.z*vC[2*wi+1] + cw.w*vD[2*wi+1];
                    uint32_t p0 = split_pack(s0), p1 = split_pack(s1);
                    hq[wi] = __byte_perm(p0, p1, 0x5410);
                    lq[wi] = __byte_perm(p0, p1, 0x7632);
                }
                uint32_t d = swz(pl, jh*4 + q);
                *(uint4*)(smem + FS_AH + d) = make_uint4(hq[0],hq[1],hq[2],hq[3]);
                *(uint4*)(smem + FS_AL + d) = make_uint4(lq[0],lq[1],lq[2],lq[3]);
            }
        }
        __syncthreads();

        // MMA: 4 k-steps; warp covers 32 px x 32 o
        #pragma unroll
        for (int ks = 0; ks < 4; ks++) {
            uint32_t aH[2][4], aL[2][4];
            #pragma unroll
            for (int mt = 0; mt < 2; mt++) {
                uint32_t aAH = sbu + FS_AH + swz(wq*32 + mt*16 + laneA, ks*2 + kbA);
                ldm_x4(aH[mt][0],aH[mt][1],aH[mt][2],aH[mt][3], aAH);
                ldm_x4(aL[mt][0],aL[mt][1],aL[mt][2],aL[mt][3], aAH + (FS_AL - FS_AH));
            }
            #pragma unroll
            for (int np = 0; np < 2; np++) {
                uint32_t aB = sbu + FS_BH + swz(wn*32 + np*16 + rowB0, ks*2 + kbB);
                uint32_t bh0,bh1,bh2,bh3, bl0,bl1,bl2,bl3;
                ldm_x4(bh0,bh1,bh2,bh3, aB);
                ldm_x4(bl0,bl1,bl2,bl3, aB + (FS_BL - FS_BH));
                #pragma unroll
                for (int mt = 0; mt < 2; mt++) {
                    mma_bf16(acc[mt][2*np],   aH[mt][0],aH[mt][1],aH[mt][2],aH[mt][3], bh0,bh1);
                    mma_bf16(acc[mt][2*np],   aH[mt][0],aH[mt][1],aH[mt][2],aH[mt][3], bl0,bl1);
                    mma_bf16(acc[mt][2*np],   aL[mt][0],aL[mt][1],aL[mt][2],aL[mt][3], bh0,bh1);
                    mma_bf16(acc[mt][2*np+1], aH[mt][0],aH[mt][1],aH[mt][2],aH[mt][3], bh2,bh3);
                    mma_bf16(acc[mt][2*np+1], aH[mt][0],aH[mt][1],aH[mt][2],aH[mt][3], bl2,bl3);
                    mma_bf16(acc[mt][2*np+1], aL[mt][0],aL[mt][1],aL[mt][2],aL[mt][3], bh2,bh3);
                }
            }
        }
    }

    // epilogue
    const size_t bofs = (size_t)b*Cv*HWv;
    #pragma unroll
    for (int mt = 0; mt < 2; mt++) {
        const int px0 = P0 + wq*32 + mt*16 + g;
        #pragma unroll
        for (int nt = 0; nt < 4; nt++) {
            #pragma unroll
            for (int e = 0; e < 4; e++) {
                int o  = wn*32 + nt*8 + 2*tq + (e & 1);
                int pxo = px0 + (e >> 1)*8;
                float v = acc[mt][nt][e] * sSc[o] + sSh[o];
                size_t ofs = bofs + (size_t)o*HWv + pxo;
                if (identity) v += __ldg(identity + ofs);
                v = gelu_exact(v);
                out[ofs] = v;
                if (midh) midh[ofs] = __float2bfloat16(v);
            }
        }
    }
}

// ---------------------------------------------------------------------------
extern "C" void kernel_launch(void* const* d_in, const int* in_sizes, int n_in,
                              void* d_out, int out_size)
{
    const float* x      = (const float*)d_in[0];
    const float* w_om1  = (const float*)d_in[1];
    const float* b_om1  = (const float*)d_in[2];
    const float* w_dcn1 = (const float*)d_in[3];
    const float* bn1g   = (const float*)d_in[4];
    const float* bn1b   = (const float*)d_in[5];
    const float* bn1m   = (const float*)d_in[6];
    const float* bn1v   = (const float*)d_in[7];
    const float* w_om2  = (const float*)d_in[8];
    const float* b_om2  = (const float*)d_in[9];
    const float* w_dcn2 = (const float*)d_in[10];
    const float* bn2g   = (const float*)d_in[11];
    const float* bn2b   = (const float*)d_in[12];
    const float* bn2m   = (const float*)d_in[13];
    const float* bn2v   = (const float*)d_in[14];
    float* out = (float*)d_out;

    float *mid;
    __nv_bfloat16 *midh, *wh1, *wl1, *wh2, *wl2, *omh1, *omh2;
    cudaGetSymbolAddress((void**)&mid,   g_mid);
    cudaGetSymbolAddress((void**)&midh,  g_midh);
    cudaGetSymbolAddress((void**)&wh1,   g_wh1);
    cudaGetSymbolAddress((void**)&wl1,   g_wl1);
    cudaGetSymbolAddress((void**)&wh2,   g_wh2);
    cudaGetSymbolAddress((void**)&wl2,   g_wl2);
    cudaGetSymbolAddress((void**)&omh1,  g_omh1);
    cudaGetSymbolAddress((void**)&omh2,  g_omh2);

    cudaFuncSetAttribute(fused_kernel<true>,  cudaFuncAttributeMaxDynamicSharedMemorySize, FS_TOT);
    cudaFuncSetAttribute(fused_kernel<false>, cudaFuncAttributeMaxDynamicSharedMemorySize, FS_TOT);

    prep_kernel<<<(Cv*CKK + 255)/256, 256>>>(w_dcn1, w_dcn2, w_om1, w_om2);

    dim3 grid(HWv/MT, Bv);   // 200 x 4

    fused_kernel<true><<<grid, TPB, FS_TOT>>>(x, omh1, b_om1,
        x, wh1, wl1, bn1g, bn1b, bn1m, bn1v, nullptr, mid, midh);

    fused_kernel<false><<<grid, TPB, FS_TOT>>>(midh, omh2, b_om2,
        mid, wh2, wl2, bn2g, bn2b, bn2m, bn2v, x, out, nullptr);
}

// round 16
// speedup vs baseline: 1.0669x; 1.0669x over previous
#include <cuda_runtime.h>
#include <cuda_bf16.h>
#include <cuda_fp16.h>
#include <math.h>
#include <stdint.h>

#define Bv   4
#define Cv   64
#define Hv   160
#define Wv   160
#define HWv  25600
#define KKv  9
#define OMC  27
#define CKK  576

#define MT    128
#define TPB   256
#define CKC   64
#define NCH   9

// fused smem map (bytes)
#define FS_SC    0
#define FS_SH    256
#define FS_BIAS  512
#define FS_WGT   1024       // float4[1152] = 18432 -> ends 19456
#define FS_BASE  19456      // int[1152] = 4608 -> ends 24064
#define FS_AH    24576      // 16384 (offc bf16 A / dcn fp16 A)
#define FS_BH    40960      // 8192
#define FS_BL    49152      // 8192
#define FS_OM    24576      // overlaps AH (dead between phases)
#define OMST     29
#define FS_TOT   57344

__device__ float          g_mid[Bv*Cv*HWv];
__device__ __nv_bfloat16  g_midh[Bv*Cv*HWv];
// dcn weights fp16 hi/lo, k-major [o][k*64+c]
__device__ __align__(16) __half g_wh1[Cv*CKK], g_wl1[Cv*CKK];
__device__ __align__(16) __half g_wh2[Cv*CKK], g_wl2[Cv*CKK];
// offc weights bf16 hi-only, k-major
__device__ __align__(16) __nv_bfloat16 g_omh1[32*CKK];
__device__ __align__(16) __nv_bfloat16 g_omh2[32*CKK];

__device__ __forceinline__ float gelu_exact(float v) {
    return 0.5f * v * (1.0f + erff(v * 0.70710678118654752f));
}
__device__ __forceinline__ uint32_t pack_bf16x2(float lo, float hi) {
    uint32_t r;
    asm("cvt.rn.bf16x2.f32 %0, %1, %2;" : "=r"(r) : "f"(hi), "f"(lo));
    return r;
}
__device__ __forceinline__ uint32_t pack_f16x2(float lo, float hi) {
    uint32_t r;
    asm("cvt.rn.f16x2.f32 %0, %1, %2;" : "=r"(r) : "f"(hi), "f"(lo));
    return r;
}
__device__ __forceinline__ uint32_t smem_u32(const void* p) {
    uint32_t a;
    asm("{ .reg .u64 t; cvta.to.shared.u64 t, %1; cvt.u32.u64 %0, t; }" : "=r"(a) : "l"(p));
    return a;
}
__device__ __forceinline__ void mma_bf16(float* d,
    uint32_t a0, uint32_t a1, uint32_t a2, uint32_t a3, uint32_t b0, uint32_t b1)
{
    asm volatile(
        "mma.sync.aligned.m16n8k16.row.col.f32.bf16.bf16.f32 "
        "{%0,%1,%2,%3},{%4,%5,%6,%7},{%8,%9},{%0,%1,%2,%3};"
        : "+f"(d[0]), "+f"(d[1]), "+f"(d[2]), "+f"(d[3])
        : "r"(a0), "r"(a1), "r"(a2), "r"(a3), "r"(b0), "r"(b1));
}
__device__ __forceinline__ void mma_f16(float* d,
    uint32_t a0, uint32_t a1, uint32_t a2, uint32_t a3, uint32_t b0, uint32_t b1)
{
    asm volatile(
        "mma.sync.aligned.m16n8k16.row.col.f32.f16.f16.f32 "
        "{%0,%1,%2,%3},{%4,%5,%6,%7},{%8,%9},{%0,%1,%2,%3};"
        : "+f"(d[0]), "+f"(d[1]), "+f"(d[2]), "+f"(d[3])
        : "r"(a0), "r"(a1), "r"(a2), "r"(a3), "r"(b0), "r"(b1));
}
__device__ __forceinline__ void ldm_x4(uint32_t& r0, uint32_t& r1, uint32_t& r2, uint32_t& r3, uint32_t addr) {
    asm volatile("ldmatrix.sync.aligned.m8n8.x4.shared.b16 {%0,%1,%2,%3}, [%4];"
                 : "=r"(r0), "=r"(r1), "=r"(r2), "=r"(r3) : "r"(addr));
}
__device__ __forceinline__ uint32_t swz(int row, int cq) {
    return (uint32_t)(row*128 + ((cq ^ (row & 7)) << 4));
}

// ---------------------------------------------------------------------------
__global__ void prep_kernel(const float* __restrict__ wd1, const float* __restrict__ wd2,
                            const float* __restrict__ wom1, const float* __restrict__ wom2)
{
    int i = blockIdx.x * 256 + threadIdx.x;
    if (i < Cv*CKK) {
        int o = i / CKK, r = i - o*CKK;
        int c = r / 9, k = r - 9*c;
        int dst = o*CKK + k*64 + c;
        float v1 = wd1[i];
        __half h1 = __float2half(v1);
        g_wh1[dst] = h1;
        g_wl1[dst] = __float2half(v1 - __half2float(h1));
        float v2 = wd2[i];
        __half h2 = __float2half(v2);
        g_wh2[dst] = h2;
        g_wl2[dst] = __float2half(v2 - __half2float(h2));
    }
    if (i < 32*CKK) {
        int o = i / CKK, r = i - o*CKK;
        int c = r / 9, k = r - 9*c;
        int dst = o*CKK + k*64 + c;
        g_omh1[dst] = __float2bfloat16((i < OMC*CKK) ? wom1[i] : 0.f);
        g_omh2[dst] = __float2bfloat16((i < OMC*CKK) ? wom2[i] : 0.f);
    }
}

// ---------------------------------------------------------------------------
// Fused BasicBlock half: offc (1-pass bf16) -> om smem -> tables ->
// dcn (fp16 A single-tile, fp16 B hi/lo 2-pass, 32px x 32o warp tiles).
// ---------------------------------------------------------------------------
template<bool F32IN>
__global__ __launch_bounds__(TPB, 4) void fused_kernel(
    const void* __restrict__ omin,
    const __nv_bfloat16* __restrict__ omwh,
    const float* __restrict__ ombias,
    const float* __restrict__ src,
    const __half* __restrict__ wh,
    const __half* __restrict__ wl,
    const float* __restrict__ bng,
    const float* __restrict__ bnb,
    const float* __restrict__ bnm,
    const float* __restrict__ bnv,
    const float* __restrict__ identity,
    float* __restrict__ out,
    __nv_bfloat16* __restrict__ midh)
{
    extern __shared__ char smem[];
    const uint32_t sbu = smem_u32(smem);
    float*  sSc   = (float*)(smem + FS_SC);
    float*  sSh   = (float*)(smem + FS_SH);
    float*  sbias = (float*)(smem + FS_BIAS);
    float4* sWgt  = (float4*)(smem + FS_WGT);
    int*    sBase = (int*)(smem + FS_BASE);
    float*  sOm   = (float*)(smem + FS_OM);

    const int tid  = threadIdx.x, wid = tid >> 5, lane = tid & 31;
    const int g    = lane >> 2, tq = lane & 3;
    const int b    = blockIdx.y;
    const int P0   = blockIdx.x * MT;

    if (tid < 64) {
        float sc = bng[tid] * rsqrtf(bnv[tid] + 1e-5f);
        sSc[tid] = sc;
        sSh[tid] = bnb[tid] - bnm[tid]*sc;
    } else if (tid < 96) {
        int o = tid - 64;
        sbias[o] = (o < OMC) ? ombias[o] : 0.f;
    }

    const int pl = tid & 127, jh = tid >> 7;
    const int pg = P0 + pl;
    const int py = pg / Wv, px = pg - py*Wv;

    // ldmatrix lane geometry
    const int laneA = lane & 15;
    const int rowA = wid*16 + laneA;
    const int kbA  = (lane & 16) ? 1 : 0;
    const int rowB0 = (lane & 7) + ((lane & 16) ? 8 : 0);
    const int kbB   = (lane & 8) ? 1 : 0;

    // ===== Phase 1: offset/mask conv (M=128, N=32, 1-pass bf16) =====
    {
        const size_t chbase = (size_t)b*Cv*HWv + (size_t)(jh*32)*HWv;
        float acc[4][4];
        #pragma unroll
        for (int nt = 0; nt < 4; nt++)
            #pragma unroll
            for (int e = 0; e < 4; e++) acc[nt][e] = 0.f;

        for (int cc = 0; cc < NCH; cc++) {
            if (cc) __syncthreads();
            // stage B: 32 rows x 8 quads, hi only
            {
                int o = tid >> 3, cq = tid & 7;
                int gofs = o*CKK + cc*CKC + cq*8;
                *(uint4*)(smem + FS_BH + swz(o, cq)) = *(const uint4*)(omwh + gofs);
            }
            // build A: fixed tap cc
            {
                int yy = py + cc/3 - 1, xx = px + (cc % 3) - 1;
                bool val = ((unsigned)yy < (unsigned)Hv) && ((unsigned)xx < (unsigned)Wv);
                #pragma unroll
                for (int q = 0; q < 4; q++) {
                    uint32_t hq[4];
                    #pragma unroll
                    for (int wi = 0; wi < 4; wi++) {
                        int c0 = 8*q + 2*wi;
                        if (F32IN) {
                            const float* p = (const float*)omin + chbase + yy*Wv + xx;
                            float v0 = val ? __ldg(p + (size_t)c0*HWv) : 0.f;
                            float v1 = val ? __ldg(p + (size_t)(c0+1)*HWv) : 0.f;
                            hq[wi] = pack_bf16x2(v0, v1);
                        } else {
                            const __nv_bfloat16* p = (const __nv_bfloat16*)omin + chbase + yy*Wv + xx;
                            uint16_t v0 = val ? __bfloat16_as_ushort(__ldg(p + (size_t)c0*HWv)) : (uint16_t)0;
                            uint16_t v1 = val ? __bfloat16_as_ushort(__ldg(p + (size_t)(c0+1)*HWv)) : (uint16_t)0;
                            hq[wi] = (uint32_t)v0 | ((uint32_t)v1 << 16);
                        }
                    }
                    *(uint4*)(smem + FS_AH + swz(pl, jh*4 + q)) = make_uint4(hq[0],hq[1],hq[2],hq[3]);
                }
            }
            __syncthreads();
            // mma: 1 pass, N=32
            #pragma unroll
            for (int ks = 0; ks < 4; ks++) {
                uint32_t aAH = sbu + FS_AH + swz(rowA, ks*2 + kbA);
                uint32_t aH0,aH1,aH2,aH3;
                ldm_x4(aH0,aH1,aH2,aH3, aAH);
                uint32_t aB0 = sbu + FS_BH + swz(rowB0, ks*2 + kbB);
                uint32_t aB1 = sbu + FS_BH + swz(16 + rowB0, ks*2 + kbB);
                uint32_t bh0,bh1,bh2,bh3;
                ldm_x4(bh0,bh1,bh2,bh3, aB0);
                mma_bf16(acc[0], aH0,aH1,aH2,aH3, bh0,bh1);
                mma_bf16(acc[1], aH0,aH1,aH2,aH3, bh2,bh3);
                ldm_x4(bh0,bh1,bh2,bh3, aB1);
                mma_bf16(acc[2], aH0,aH1,aH2,aH3, bh0,bh1);
                mma_bf16(acc[3], aH0,aH1,aH2,aH3, bh2,bh3);
            }
        }

        __syncthreads();
        #pragma unroll
        for (int nt = 0; nt < 4; nt++) {
            #pragma unroll
            for (int e = 0; e < 4; e++) {
                int o = nt*8 + 2*tq + (e & 1);
                if (o < OMC) {
                    int p = wid*16 + g + (e >> 1)*8;
                    sOm[p*OMST + o] = acc[nt][e] + sbias[o];
                }
            }
        }
    }
    __syncthreads();

    // ===== Phase 2: gather tables from smem om =====
    for (int idx = tid; idx < KKv*MT; idx += TPB) {
        int k = idx >> 7, plt = idx & 127;
        int pxg2 = P0 + plt;
        int y = pxg2 / Wv, x = pxg2 - y*Wv;
        float dy = sOm[plt*OMST + 2*k];
        float dx = sOm[plt*OMST + 2*k+1];
        float mr = sOm[plt*OMST + 18+k];
        float m  = 1.f / (1.f + expf(-mr));
        float pyf = (float)y - 1.f + (float)(k/3) + dy;
        float pxf = (float)x - 1.f + (float)(k%3) + dx;
        float yf = floorf(pyf), xf = floorf(pxf);
        float ly = pyf - yf, lx = pxf - xf;
        int iy0 = (int)yf, ix0 = (int)xf;
        float vy0 = ((unsigned)iy0     < (unsigned)Hv) ? 1.f : 0.f;
        float vy1 = ((unsigned)(iy0+1) < (unsigned)Hv) ? 1.f : 0.f;
        float vx0 = ((unsigned)ix0     < (unsigned)Wv) ? 1.f : 0.f;
        float vx1 = ((unsigned)(ix0+1) < (unsigned)Wv) ? 1.f : 0.f;
        sWgt[idx] = make_float4((1.f-ly)*(1.f-lx)*m*vy0*vx0,
                                (1.f-ly)*lx      *m*vy0*vx1,
                                ly      *(1.f-lx)*m*vy1*vx0,
                                ly      *lx      *m*vy1*vx1);
        int iy0c = min(max(iy0,0),Hv-1), ix0c = min(max(ix0,0),Wv-1);
        int dy1 = (iy0 >= 0 && iy0 <= Hv-2) ? 1 : 0;
        int dx1 = (ix0 >= 0 && ix0 <= Wv-2) ? 1 : 0;
        sBase[idx] = iy0c | (ix0c<<8) | (dy1<<16) | (dx1<<17);
    }
    __syncthreads();

    // ===== Phase 3: DCN fp16 (A single tile, B hi/lo, 2-pass) =====
    const float* srcB = src + (size_t)b*Cv*HWv + (size_t)jh*32*HWv;
    const int wq = wid & 3, wn = wid >> 2;

    float acc[2][4][4];
    #pragma unroll
    for (int mt = 0; mt < 2; mt++)
        #pragma unroll
        for (int nt = 0; nt < 4; nt++)
            #pragma unroll
            for (int e = 0; e < 4; e++) acc[mt][nt][e] = 0.f;

    for (int cc = 0; cc < NCH; cc++) {
        if (cc) __syncthreads();

        // stage B chunk hi/lo: 64 rows x 8 quads (uint4)
        #pragma unroll
        for (int it = 0; it < 2; it++) {
            int idx = it*TPB + tid;
            int o = idx >> 3, cq = idx & 7;
            int gofs = o*CKK + cc*CKC + cq*8;
            uint32_t d = swz(o, cq);
            *(uint4*)(smem + FS_BH + d) = *(const uint4*)(wh + gofs);
            *(uint4*)(smem + FS_BL + d) = *(const uint4*)(wl + gofs);
        }

        // sample A chunk: fixed tap cc -> fp16 tile
        {
            int gi = cc*MT + pl;
            float4 cw = sWgt[gi];
            int ev = sBase[gi];
            int iy0 = ev & 255, ix0 = (ev>>8) & 255;
            int iy1 = iy0 + ((ev>>16)&1), ix1 = ix0 + ((ev>>17)&1);
            const float* pA = srcB + iy0*Wv + ix0;
            const float* pB = srcB + iy0*Wv + ix1;
            const float* pC = srcB + iy1*Wv + ix0;
            const float* pD = srcB + iy1*Wv + ix1;
            #pragma unroll
            for (int q = 0; q < 4; q++) {
                float vA[8], vB[8], vC[8], vD[8];
                #pragma unroll
                for (int ci = 0; ci < 8; ci++) {
                    size_t co = (size_t)(8*q + ci)*HWv;
                    vA[ci] = __ldg(pA + co);
                    vB[ci] = __ldg(pB + co);
                    vC[ci] = __ldg(pC + co);
                    vD[ci] = __ldg(pD + co);
                }
                uint32_t hq[4];
                #pragma unroll
                for (int wi = 0; wi < 4; wi++) {
                    float s0 = cw.x*vA[2*wi]   + cw.y*vB[2*wi]
                             + cw.z*vC[2*wi]   + cw.w*vD[2*wi];
                    float s1 = cw.x*vA[2*wi+1] + cw.y*vB[2*wi+1]
                             + cw.z*vC[2*wi+1] + cw.w*vD[2*wi+1];
                    hq[wi] = pack_f16x2(s0, s1);
                }
                *(uint4*)(smem + FS_AH + swz(pl, jh*4 + q)) = make_uint4(hq[0],hq[1],hq[2],hq[3]);
            }
        }
        __syncthreads();

        // MMA: 4 k-steps; warp covers 32 px x 32 o; 2 passes (bH, bL)
        #pragma unroll
        for (int ks = 0; ks < 4; ks++) {
            uint32_t aH[2][4];
            #pragma unroll
            for (int mt = 0; mt < 2; mt++) {
                uint32_t aAH = sbu + FS_AH + swz(wq*32 + mt*16 + laneA, ks*2 + kbA);
                ldm_x4(aH[mt][0],aH[mt][1],aH[mt][2],aH[mt][3], aAH);
            }
            #pragma unroll
            for (int np = 0; np < 2; np++) {
                uint32_t aB = sbu + FS_BH + swz(wn*32 + np*16 + rowB0, ks*2 + kbB);
                uint32_t bh0,bh1,bh2,bh3, bl0,bl1,bl2,bl3;
                ldm_x4(bh0,bh1,bh2,bh3, aB);
                ldm_x4(bl0,bl1,bl2,bl3, aB + (FS_BL - FS_BH));
                #pragma unroll
                for (int mt = 0; mt < 2; mt++) {
                    mma_f16(acc[mt][2*np],   aH[mt][0],aH[mt][1],aH[mt][2],aH[mt][3], bh0,bh1);
                    mma_f16(acc[mt][2*np],   aH[mt][0],aH[mt][1],aH[mt][2],aH[mt][3], bl0,bl1);
                    mma_f16(acc[mt][2*np+1], aH[mt][0],aH[mt][1],aH[mt][2],aH[mt][3], bh2,bh3);
                    mma_f16(acc[mt][2*np+1], aH[mt][0],aH[mt][1],aH[mt][2],aH[mt][3], bl2,bl3);
                }
            }
        }
    }

    // epilogue: BN (+residual) + exact GELU (+ bf16 copy for layer 1)
    const size_t bofs = (size_t)b*Cv*HWv;
    #pragma unroll
    for (int mt = 0; mt < 2; mt++) {
        const int px0 = P0 + wq*32 + mt*16 + g;
        #pragma unroll
        for (int nt = 0; nt < 4; nt++) {
            #pragma unroll
            for (int e = 0; e < 4; e++) {
                int o  = wn*32 + nt*8 + 2*tq + (e & 1);
                int pxo = px0 + (e >> 1)*8;
                float v = acc[mt][nt][e] * sSc[o] + sSh[o];
                size_t ofs = bofs + (size_t)o*HWv + pxo;
                if (identity) v += __ldg(identity + ofs);
                v = gelu_exact(v);
                out[ofs] = v;
                if (midh) midh[ofs] = __float2bfloat16(v);
            }
        }
    }
}

// ---------------------------------------------------------------------------
extern "C" void kernel_launch(void* const* d_in, const int* in_sizes, int n_in,
                              void* d_out, int out_size)
{
    const float* x      = (const float*)d_in[0];
    const float* w_om1  = (const float*)d_in[1];
    const float* b_om1  = (const float*)d_in[2];
    const float* w_dcn1 = (const float*)d_in[3];
    const float* bn1g   = (const float*)d_in[4];
    const float* bn1b   = (const float*)d_in[5];
    const float* bn1m   = (const float*)d_in[6];
    const float* bn1v   = (const float*)d_in[7];
    const float* w_om2  = (const float*)d_in[8];
    const float* b_om2  = (const float*)d_in[9];
    const float* w_dcn2 = (const float*)d_in[10];
    const float* bn2g   = (const float*)d_in[11];
    const float* bn2b   = (const float*)d_in[12];
    const float* bn2m   = (const float*)d_in[13];
    const float* bn2v   = (const float*)d_in[14];
    float* out = (float*)d_out;

    float *mid;
    __nv_bfloat16 *midh, *omh1, *omh2;
    __half *wh1, *wl1, *wh2, *wl2;
    cudaGetSymbolAddress((void**)&mid,   g_mid);
    cudaGetSymbolAddress((void**)&midh,  g_midh);
    cudaGetSymbolAddress((void**)&wh1,   g_wh1);
    cudaGetSymbolAddress((void**)&wl1,   g_wl1);
    cudaGetSymbolAddress((void**)&wh2,   g_wh2);
    cudaGetSymbolAddress((void**)&wl2,   g_wl2);
    cudaGetSymbolAddress((void**)&omh1,  g_omh1);
    cudaGetSymbolAddress((void**)&omh2,  g_omh2);

    cudaFuncSetAttribute(fused_kernel<true>,  cudaFuncAttributeMaxDynamicSharedMemorySize, FS_TOT);
    cudaFuncSetAttribute(fused_kernel<false>, cudaFuncAttributeMaxDynamicSharedMemorySize, FS_TOT);

    prep_kernel<<<(Cv*CKK + 255)/256, 256>>>(w_dcn1, w_dcn2, w_om1, w_om2);

    dim3 grid(HWv/MT, Bv);   // 200 x 4

    fused_kernel<true><<<grid, TPB, FS_TOT>>>(x, omh1, b_om1,
        x, wh1, wl1, bn1g, bn1b, bn1m, bn1v, nullptr, mid, midh);

    fused_kernel<false><<<grid, TPB, FS_TOT>>>(midh, omh2, b_om2,
        mid, wh2, wl2, bn2g, bn2b, bn2m, bn2v, x, out, nullptr);
}

// round 17
// speedup vs baseline: 1.1145x; 1.0446x over previous
#include <cuda_runtime.h>
#include <cuda_bf16.h>
#include <cuda_fp16.h>
#include <math.h>
#include <stdint.h>

#define Bv   4
#define Cv   64
#define Hv   160
#define Wv   160
#define HWv  25600
#define KKv  9
#define OMC  27
#define CKK  576

#define MT    128
#define TPB   256
#define CKC   64
#define NCH   9

// fused smem map (bytes)
#define FS_SC    0
#define FS_SH    256
#define FS_BIAS  512
#define FS_WGT   1024       // float4[1152] = 18432 -> ends 19456
#define FS_BASE  19456      // int[1152] = 4608 -> ends 24064
#define FS_AH    24576      // 16384 (offc bf16 A / dcn fp16 A)
#define FS_BH    40960      // 8192
#define FS_BL    49152      // 8192
#define FS_OM    24576      // overlaps AH (dead between phases)
#define OMST     29
#define FS_TOT   57344

__device__ float          g_mid[Bv*Cv*HWv];
__device__ __nv_bfloat16  g_midh[Bv*Cv*HWv];
// dcn weights fp16 hi/lo, k-major [o][k*64+c]
__device__ __align__(16) __half g_wh1[Cv*CKK], g_wl1[Cv*CKK];
__device__ __align__(16) __half g_wh2[Cv*CKK], g_wl2[Cv*CKK];
// offc weights bf16 hi-only, k-major
__device__ __align__(16) __nv_bfloat16 g_omh1[32*CKK];
__device__ __align__(16) __nv_bfloat16 g_omh2[32*CKK];

__device__ __forceinline__ float gelu_exact(float v) {
    return 0.5f * v * (1.0f + erff(v * 0.70710678118654752f));
}
__device__ __forceinline__ uint32_t pack_bf16x2(float lo, float hi) {
    uint32_t r;
    asm("cvt.rn.bf16x2.f32 %0, %1, %2;" : "=r"(r) : "f"(hi), "f"(lo));
    return r;
}
__device__ __forceinline__ uint32_t pack_f16x2(float lo, float hi) {
    uint32_t r;
    asm("cvt.rn.f16x2.f32 %0, %1, %2;" : "=r"(r) : "f"(hi), "f"(lo));
    return r;
}
__device__ __forceinline__ uint32_t smem_u32(const void* p) {
    uint32_t a;
    asm("{ .reg .u64 t; cvta.to.shared.u64 t, %1; cvt.u32.u64 %0, t; }" : "=r"(a) : "l"(p));
    return a;
}
__device__ __forceinline__ void mma_bf16(float* d,
    uint32_t a0, uint32_t a1, uint32_t a2, uint32_t a3, uint32_t b0, uint32_t b1)
{
    asm volatile(
        "mma.sync.aligned.m16n8k16.row.col.f32.bf16.bf16.f32 "
        "{%0,%1,%2,%3},{%4,%5,%6,%7},{%8,%9},{%0,%1,%2,%3};"
        : "+f"(d[0]), "+f"(d[1]), "+f"(d[2]), "+f"(d[3])
        : "r"(a0), "r"(a1), "r"(a2), "r"(a3), "r"(b0), "r"(b1));
}
__device__ __forceinline__ void mma_f16(float* d,
    uint32_t a0, uint32_t a1, uint32_t a2, uint32_t a3, uint32_t b0, uint32_t b1)
{
    asm volatile(
        "mma.sync.aligned.m16n8k16.row.col.f32.f16.f16.f32 "
        "{%0,%1,%2,%3},{%4,%5,%6,%7},{%8,%9},{%0,%1,%2,%3};"
        : "+f"(d[0]), "+f"(d[1]), "+f"(d[2]), "+f"(d[3])
        : "r"(a0), "r"(a1), "r"(a2), "r"(a3), "r"(b0), "r"(b1));
}
__device__ __forceinline__ void ldm_x4(uint32_t& r0, uint32_t& r1, uint32_t& r2, uint32_t& r3, uint32_t addr) {
    asm volatile("ldmatrix.sync.aligned.m8n8.x4.shared.b16 {%0,%1,%2,%3}, [%4];"
                 : "=r"(r0), "=r"(r1), "=r"(r2), "=r"(r3) : "r"(addr));
}
__device__ __forceinline__ uint32_t swz(int row, int cq) {
    return (uint32_t)(row*128 + ((cq ^ (row & 7)) << 4));
}

// ---------------------------------------------------------------------------
__global__ void prep_kernel(const float* __restrict__ wd1, const float* __restrict__ wd2,
                            const float* __restrict__ wom1, const float* __restrict__ wom2)
{
    int i = blockIdx.x * 256 + threadIdx.x;
    if (i < Cv*CKK) {
        int o = i / CKK, r = i - o*CKK;
        int c = r / 9, k = r - 9*c;
        int dst = o*CKK + k*64 + c;
        float v1 = wd1[i];
        __half h1 = __float2half(v1);
        g_wh1[dst] = h1;
        g_wl1[dst] = __float2half(v1 - __half2float(h1));
        float v2 = wd2[i];
        __half h2 = __float2half(v2);
        g_wh2[dst] = h2;
        g_wl2[dst] = __float2half(v2 - __half2float(h2));
    }
    if (i < 32*CKK) {
        int o = i / CKK, r = i - o*CKK;
        int c = r / 9, k = r - 9*c;
        int dst = o*CKK + k*64 + c;
        g_omh1[dst] = __float2bfloat16((i < OMC*CKK) ? wom1[i] : 0.f);
        g_omh2[dst] = __float2bfloat16((i < OMC*CKK) ? wom2[i] : 0.f);
    }
}

// ---------------------------------------------------------------------------
// Fused BasicBlock half: offc (1-pass bf16) -> om smem -> tables ->
// dcn (fp16 A single-tile, fp16 B hi/lo 2-pass, 32px x 32o warp tiles).
// ---------------------------------------------------------------------------
template<bool F32IN>
__global__ __launch_bounds__(TPB, 3) void fused_kernel(
    const void* __restrict__ omin,
    const __nv_bfloat16* __restrict__ omwh,
    const float* __restrict__ ombias,
    const float* __restrict__ src,
    const __half* __restrict__ wh,
    const __half* __restrict__ wl,
    const float* __restrict__ bng,
    const float* __restrict__ bnb,
    const float* __restrict__ bnm,
    const float* __restrict__ bnv,
    const float* __restrict__ identity,
    float* __restrict__ out,
    __nv_bfloat16* __restrict__ midh)
{
    extern __shared__ char smem[];
    const uint32_t sbu = smem_u32(smem);
    float*  sSc   = (float*)(smem + FS_SC);
    float*  sSh   = (float*)(smem + FS_SH);
    float*  sbias = (float*)(smem + FS_BIAS);
    float4* sWgt  = (float4*)(smem + FS_WGT);
    int*    sBase = (int*)(smem + FS_BASE);
    float*  sOm   = (float*)(smem + FS_OM);

    const int tid  = threadIdx.x, wid = tid >> 5, lane = tid & 31;
    const int g    = lane >> 2, tq = lane & 3;
    const int b    = blockIdx.y;
    const int P0   = blockIdx.x * MT;

    if (tid < 64) {
        float sc = bng[tid] * rsqrtf(bnv[tid] + 1e-5f);
        sSc[tid] = sc;
        sSh[tid] = bnb[tid] - bnm[tid]*sc;
    } else if (tid < 96) {
        int o = tid - 64;
        sbias[o] = (o < OMC) ? ombias[o] : 0.f;
    }

    const int pl = tid & 127, jh = tid >> 7;
    const int pg = P0 + pl;
    const int py = pg / Wv, px = pg - py*Wv;

    // ldmatrix lane geometry
    const int laneA = lane & 15;
    const int rowA = wid*16 + laneA;
    const int kbA  = (lane & 16) ? 1 : 0;
    const int rowB0 = (lane & 7) + ((lane & 16) ? 8 : 0);
    const int kbB   = (lane & 8) ? 1 : 0;

    // ===== Phase 1: offset/mask conv (M=128, N=32, 1-pass bf16) =====
    {
        const size_t chbase = (size_t)b*Cv*HWv + (size_t)(jh*32)*HWv;
        float acc[4][4];
        #pragma unroll
        for (int nt = 0; nt < 4; nt++)
            #pragma unroll
            for (int e = 0; e < 4; e++) acc[nt][e] = 0.f;

        for (int cc = 0; cc < NCH; cc++) {
            if (cc) __syncthreads();
            // stage B: 32 rows x 8 quads, hi only
            {
                int o = tid >> 3, cq = tid & 7;
                int gofs = o*CKK + cc*CKC + cq*8;
                *(uint4*)(smem + FS_BH + swz(o, cq)) = *(const uint4*)(omwh + gofs);
            }
            // build A: fixed tap cc
            {
                int yy = py + cc/3 - 1, xx = px + (cc % 3) - 1;
                bool val = ((unsigned)yy < (unsigned)Hv) && ((unsigned)xx < (unsigned)Wv);
                #pragma unroll
                for (int q = 0; q < 4; q++) {
                    uint32_t hq[4];
                    #pragma unroll
                    for (int wi = 0; wi < 4; wi++) {
                        int c0 = 8*q + 2*wi;
                        if (F32IN) {
                            const float* p = (const float*)omin + chbase + yy*Wv + xx;
                            float v0 = val ? __ldg(p + (size_t)c0*HWv) : 0.f;
                            float v1 = val ? __ldg(p + (size_t)(c0+1)*HWv) : 0.f;
                            hq[wi] = pack_bf16x2(v0, v1);
                        } else {
                            const __nv_bfloat16* p = (const __nv_bfloat16*)omin + chbase + yy*Wv + xx;
                            uint16_t v0 = val ? __bfloat16_as_ushort(__ldg(p + (size_t)c0*HWv)) : (uint16_t)0;
                            uint16_t v1 = val ? __bfloat16_as_ushort(__ldg(p + (size_t)(c0+1)*HWv)) : (uint16_t)0;
                            hq[wi] = (uint32_t)v0 | ((uint32_t)v1 << 16);
                        }
                    }
                    *(uint4*)(smem + FS_AH + swz(pl, jh*4 + q)) = make_uint4(hq[0],hq[1],hq[2],hq[3]);
                }
            }
            __syncthreads();
            // mma: 1 pass, N=32
            #pragma unroll
            for (int ks = 0; ks < 4; ks++) {
                uint32_t aAH = sbu + FS_AH + swz(rowA, ks*2 + kbA);
                uint32_t aH0,aH1,aH2,aH3;
                ldm_x4(aH0,aH1,aH2,aH3, aAH);
                uint32_t aB0 = sbu + FS_BH + swz(rowB0, ks*2 + kbB);
                uint32_t aB1 = sbu + FS_BH + swz(16 + rowB0, ks*2 + kbB);
                uint32_t bh0,bh1,bh2,bh3;
                ldm_x4(bh0,bh1,bh2,bh3, aB0);
                mma_bf16(acc[0], aH0,aH1,aH2,aH3, bh0,bh1);
                mma_bf16(acc[1], aH0,aH1,aH2,aH3, bh2,bh3);
                ldm_x4(bh0,bh1,bh2,bh3, aB1);
                mma_bf16(acc[2], aH0,aH1,aH2,aH3, bh0,bh1);
                mma_bf16(acc[3], aH0,aH1,aH2,aH3, bh2,bh3);
            }
        }

        __syncthreads();
        #pragma unroll
        for (int nt = 0; nt < 4; nt++) {
            #pragma unroll
            for (int e = 0; e < 4; e++) {
                int o = nt*8 + 2*tq + (e & 1);
                if (o < OMC) {
                    int p = wid*16 + g + (e >> 1)*8;
                    sOm[p*OMST + o] = acc[nt][e] + sbias[o];
                }
            }
        }
    }
    __syncthreads();

    // ===== Phase 2: gather tables from smem om =====
    for (int idx = tid; idx < KKv*MT; idx += TPB) {
        int k = idx >> 7, plt = idx & 127;
        int pxg2 = P0 + plt;
        int y = pxg2 / Wv, x = pxg2 - y*Wv;
        float dy = sOm[plt*OMST + 2*k];
        float dx = sOm[plt*OMST + 2*k+1];
        float mr = sOm[plt*OMST + 18+k];
        float m  = 1.f / (1.f + expf(-mr));
        float pyf = (float)y - 1.f + (float)(k/3) + dy;
        float pxf = (float)x - 1.f + (float)(k%3) + dx;
        float yf = floorf(pyf), xf = floorf(pxf);
        float ly = pyf - yf, lx = pxf - xf;
        int iy0 = (int)yf, ix0 = (int)xf;
        float vy0 = ((unsigned)iy0     < (unsigned)Hv) ? 1.f : 0.f;
        float vy1 = ((unsigned)(iy0+1) < (unsigned)Hv) ? 1.f : 0.f;
        float vx0 = ((unsigned)ix0     < (unsigned)Wv) ? 1.f : 0.f;
        float vx1 = ((unsigned)(ix0+1) < (unsigned)Wv) ? 1.f : 0.f;
        sWgt[idx] = make_float4((1.f-ly)*(1.f-lx)*m*vy0*vx0,
                                (1.f-ly)*lx      *m*vy0*vx1,
                                ly      *(1.f-lx)*m*vy1*vx0,
                                ly      *lx      *m*vy1*vx1);
        int iy0c = min(max(iy0,0),Hv-1), ix0c = min(max(ix0,0),Wv-1);
        int dy1 = (iy0 >= 0 && iy0 <= Hv-2) ? 1 : 0;
        int dx1 = (ix0 >= 0 && ix0 <= Wv-2) ? 1 : 0;
        sBase[idx] = iy0c | (ix0c<<8) | (dy1<<16) | (dx1<<17);
    }
    __syncthreads();

    // ===== Phase 3: DCN fp16 (A single tile, B hi/lo, 2-pass) =====
    const float* srcB = src + (size_t)b*Cv*HWv + (size_t)jh*32*HWv;
    const int wq = wid & 3, wn = wid >> 2;

    float acc[2][4][4];
    #pragma unroll
    for (int mt = 0; mt < 2; mt++)
        #pragma unroll
        for (int nt = 0; nt < 4; nt++)
            #pragma unroll
            for (int e = 0; e < 4; e++) acc[mt][nt][e] = 0.f;

    for (int cc = 0; cc < NCH; cc++) {
        if (cc) __syncthreads();

        // stage B chunk hi/lo: 64 rows x 8 quads (uint4)
        #pragma unroll
        for (int it = 0; it < 2; it++) {
            int idx = it*TPB + tid;
            int o = idx >> 3, cq = idx & 7;
            int gofs = o*CKK + cc*CKC + cq*8;
            uint32_t d = swz(o, cq);
            *(uint4*)(smem + FS_BH + d) = *(const uint4*)(wh + gofs);
            *(uint4*)(smem + FS_BL + d) = *(const uint4*)(wl + gofs);
        }

        // sample A chunk: fixed tap cc -> fp16 tile
        {
            int gi = cc*MT + pl;
            float4 cw = sWgt[gi];
            int ev = sBase[gi];
            int iy0 = ev & 255, ix0 = (ev>>8) & 255;
            int iy1 = iy0 + ((ev>>16)&1), ix1 = ix0 + ((ev>>17)&1);
            const float* pA = srcB + iy0*Wv + ix0;
            const float* pB = srcB + iy0*Wv + ix1;
            const float* pC = srcB + iy1*Wv + ix0;
            const float* pD = srcB + iy1*Wv + ix1;
            #pragma unroll
            for (int q = 0; q < 4; q++) {
                float vA[8], vB[8], vC[8], vD[8];
                #pragma unroll
                for (int ci = 0; ci < 8; ci++) {
                    size_t co = (size_t)(8*q + ci)*HWv;
                    vA[ci] = __ldg(pA + co);
                    vB[ci] = __ldg(pB + co);
                    vC[ci] = __ldg(pC + co);
                    vD[ci] = __ldg(pD + co);
                }
                uint32_t hq[4];
                #pragma unroll
                for (int wi = 0; wi < 4; wi++) {
                    float s0 = cw.x*vA[2*wi]   + cw.y*vB[2*wi]
                             + cw.z*vC[2*wi]   + cw.w*vD[2*wi];
                    float s1 = cw.x*vA[2*wi+1] + cw.y*vB[2*wi+1]
                             + cw.z*vC[2*wi+1] + cw.w*vD[2*wi+1];
                    hq[wi] = pack_f16x2(s0, s1);
                }
                *(uint4*)(smem + FS_AH + swz(pl, jh*4 + q)) = make_uint4(hq[0],hq[1],hq[2],hq[3]);
            }
        }
        __syncthreads();

        // MMA: 4 k-steps; warp covers 32 px x 32 o; 2 passes (bH, bL)
        #pragma unroll
        for (int ks = 0; ks < 4; ks++) {
            uint32_t aH[2][4];
            #pragma unroll
            for (int mt = 0; mt < 2; mt++) {
                uint32_t aAH = sbu + FS_AH + swz(wq*32 + mt*16 + laneA, ks*2 + kbA);
                ldm_x4(aH[mt][0],aH[mt][1],aH[mt][2],aH[mt][3], aAH);
            }
            #pragma unroll
            for (int np = 0; np < 2; np++) {
                uint32_t aB = sbu + FS_BH + swz(wn*32 + np*16 + rowB0, ks*2 + kbB);
                uint32_t bh0,bh1,bh2,bh3, bl0,bl1,bl2,bl3;
                ldm_x4(bh0,bh1,bh2,bh3, aB);
                ldm_x4(bl0,bl1,bl2,bl3, aB + (FS_BL - FS_BH));
                #pragma unroll
                for (int mt = 0; mt < 2; mt++) {
                    mma_f16(acc[mt][2*np],   aH[mt][0],aH[mt][1],aH[mt][2],aH[mt][3], bh0,bh1);
                    mma_f16(acc[mt][2*np],   aH[mt][0],aH[mt][1],aH[mt][2],aH[mt][3], bl0,bl1);
                    mma_f16(acc[mt][2*np+1], aH[mt][0],aH[mt][1],aH[mt][2],aH[mt][3], bh2,bh3);
                    mma_f16(acc[mt][2*np+1], aH[mt][0],aH[mt][1],aH[mt][2],aH[mt][3], bl2,bl3);
                }
            }
        }
    }

    // epilogue: BN (+residual) + exact GELU (+ bf16 copy for layer 1)
    const size_t bofs = (size_t)b*Cv*HWv;
    #pragma unroll
    for (int mt = 0; mt < 2; mt++) {
        const int px0 = P0 + wq*32 + mt*16 + g;
        #pragma unroll
        for (int nt = 0; nt < 4; nt++) {
            #pragma unroll
            for (int e = 0; e < 4; e++) {
                int o  = wn*32 + nt*8 + 2*tq + (e & 1);
                int pxo = px0 + (e >> 1)*8;
                float v = acc[mt][nt][e] * sSc[o] + sSh[o];
                size_t ofs = bofs + (size_t)o*HWv + pxo;
                if (identity) v += __ldg(identity + ofs);
                v = gelu_exact(v);
                out[ofs] = v;
                if (midh) midh[ofs] = __float2bfloat16(v);
            }
        }
    }
}

// ---------------------------------------------------------------------------
extern "C" void kernel_launch(void* const* d_in, const int* in_sizes, int n_in,
                              void* d_out, int out_size)
{
    const float* x      = (const float*)d_in[0];
    const float* w_om1  = (const float*)d_in[1];
    const float* b_om1  = (const float*)d_in[2];
    const float* w_dcn1 = (const float*)d_in[3];
    const float* bn1g   = (const float*)d_in[4];
    const float* bn1b   = (const float*)d_in[5];
    const float* bn1m   = (const float*)d_in[6];
    const float* bn1v   = (const float*)d_in[7];
    const float* w_om2  = (const float*)d_in[8];
    const float* b_om2  = (const float*)d_in[9];
    const float* w_dcn2 = (const float*)d_in[10];
    const float* bn2g   = (const float*)d_in[11];
    const float* bn2b   = (const float*)d_in[12];
    const float* bn2m   = (const float*)d_in[13];
    const float* bn2v   = (const float*)d_in[14];
    float* out = (float*)d_out;

    float *mid;
    __nv_bfloat16 *midh, *omh1, *omh2;
    __half *wh1, *wl1, *wh2, *wl2;
    cudaGetSymbolAddress((void**)&mid,   g_mid);
    cudaGetSymbolAddress((void**)&midh,  g_midh);
    cudaGetSymbolAddress((void**)&wh1,   g_wh1);
    cudaGetSymbolAddress((void**)&wl1,   g_wl1);
    cudaGetSymbolAddress((void**)&wh2,   g_wh2);
    cudaGetSymbolAddress((void**)&wl2,   g_wl2);
    cudaGetSymbolAddress((void**)&omh1,  g_omh1);
    cudaGetSymbolAddress((void**)&omh2,  g_omh2);

    cudaFuncSetAttribute(fused_kernel<true>,  cudaFuncAttributeMaxDynamicSharedMemorySize, FS_TOT);
    cudaFuncSetAttribute(fused_kernel<false>, cudaFuncAttributeMaxDynamicSharedMemorySize, FS_TOT);

    prep_kernel<<<(Cv*CKK + 255)/256, 256>>>(w_dcn1, w_dcn2, w_om1, w_om2);

    dim3 grid(HWv/MT, Bv);   // 200 x 4

    fused_kernel<true><<<grid, TPB, FS_TOT>>>(x, omh1, b_om1,
        x, wh1, wl1, bn1g, bn1b, bn1m, bn1v, nullptr, mid, midh);

    fused_kernel<false><<<grid, TPB, FS_TOT>>>(midh, omh2, b_om2,
        mid, wh2, wl2, bn2g, bn2b, bn2m, bn2v, x, out, nullptr);
}